// round 7
// baseline (speedup 1.0000x reference)
#include <cuda_runtime.h>
#include <cstdint>

#define BSZ 4
#define NN  512
#define DD  128

// ---------------- scratch (no allocations allowed) ----------------
__device__ __align__(16) float g_q [BSZ * NN * DD];
__device__ __align__(16) float g_Ek[BSZ * NN * DD];
__device__ __align__(16) float g_V [BSZ * NN * DD];
__device__ __align__(16) unsigned long long g_P2[NN * NN];   // (expP, expP) pairs

// packed f32x2 FMA: d.lo += a.lo*b.lo ; d.hi += a.hi*b.hi
__device__ __forceinline__ void ffma2(unsigned long long& d,
                                      unsigned long long a,
                                      unsigned long long b) {
    asm("fma.rn.f32x2 %0, %1, %2, %0;" : "+l"(d) : "l"(a), "l"(b));
}
__device__ __forceinline__ unsigned long long dup_f32(float f) {
    unsigned int u = __float_as_uint(f);
    return ((unsigned long long)u << 32) | (unsigned long long)u;
}
__device__ __forceinline__ float lo_f(unsigned long long u) { return __uint_as_float((unsigned)u); }
__device__ __forceinline__ float hi_f(unsigned long long u) { return __uint_as_float((unsigned)(u >> 32)); }

// =============== kernel 1: fused projections (blocks 0..95) + exp(pos_bias) (96..159) ===============
// (unchanged from previous round — attribution: this round only touches aft_kernel)
__global__ __launch_bounds__(256) void prep_kernel(
    const float* __restrict__ X,
    const float* __restrict__ Wq, const float* __restrict__ bq,
    const float* __restrict__ Wk, const float* __restrict__ bk,
    const float* __restrict__ Wv, const float* __restrict__ bv,
    const float* __restrict__ pb)
{
    const int tid = threadIdx.x;
    const int bx  = blockIdx.x;

    if (bx >= 96) {   // ---- exp(pos_bias): 64 blocks x 4096 elems, 16/thread ----
        const int base = (bx - 96) * 4096;
        #pragma unroll
        for (int l = 0; l < 4; l++) {
            int i = base + l * 1024 + tid * 4;
            float4 v = *(const float4*)&pb[i];
            ulonglong2 o0, o1;
            o0.x = dup_f32(__expf(v.x)); o0.y = dup_f32(__expf(v.y));
            o1.x = dup_f32(__expf(v.z)); o1.y = dup_f32(__expf(v.w));
            *(ulonglong2*)&g_P2[i]     = o0;
            *(ulonglong2*)&g_P2[i + 2] = o1;
        }
        return;
    }

    __shared__ __align__(16) unsigned long long Xs2[64][34];
    __shared__ __align__(16) float Ws[32][132];

    const int p  = bx >> 5;
    const int r0 = (bx & 31) * 64;
    const float* W    = (p == 0) ? Wq : (p == 1) ? Wk : Wv;
    const float* bias = (p == 0) ? bq : (p == 1) ? bk : bv;
    float*       Out  = (p == 0) ? g_q : (p == 1) ? g_Ek : g_V;

    const int tx = tid & 31;
    const int ty = tid >> 5;

    unsigned long long acc[8][2] = {};
    float4 ax[2], wx[4];

    #pragma unroll
    for (int l = 0; l < 2; l++) {
        int idx = tid + l * 256, row = idx >> 3, c4 = idx & 7;
        ax[l] = *(const float4*)&X[(r0 + row) * DD + 4 * c4];
    }
    #pragma unroll
    for (int l = 0; l < 4; l++) {
        int idx = tid + l * 256, k4 = idx & 7, e = idx >> 3;
        wx[l] = *(const float4*)&W[e * DD + 4 * k4];
    }

    for (int kt = 0; kt < 4; kt++) {
        #pragma unroll
        for (int l = 0; l < 2; l++) {
            int idx = tid + l * 256, row = idx >> 3, c4 = idx & 7;
            ulonglong2 u0, u1;
            u0.x = dup_f32(ax[l].x); u0.y = dup_f32(ax[l].y);
            u1.x = dup_f32(ax[l].z); u1.y = dup_f32(ax[l].w);
            *(ulonglong2*)&Xs2[row][4 * c4]     = u0;
            *(ulonglong2*)&Xs2[row][4 * c4 + 2] = u1;
        }
        #pragma unroll
        for (int l = 0; l < 4; l++) {
            int idx = tid + l * 256, k4 = idx & 7, e = idx >> 3;
            Ws[4 * k4 + 0][e] = wx[l].x;
            Ws[4 * k4 + 1][e] = wx[l].y;
            Ws[4 * k4 + 2][e] = wx[l].z;
            Ws[4 * k4 + 3][e] = wx[l].w;
        }
        __syncthreads();

        if (kt < 3) {
            int kk = (kt + 1) * 32;
            #pragma unroll
            for (int l = 0; l < 2; l++) {
                int idx = tid + l * 256, row = idx >> 3, c4 = idx & 7;
                ax[l] = *(const float4*)&X[(r0 + row) * DD + kk + 4 * c4];
            }
            #pragma unroll
            for (int l = 0; l < 4; l++) {
                int idx = tid + l * 256, k4 = idx & 7, e = idx >> 3;
                wx[l] = *(const float4*)&W[e * DD + kk + 4 * k4];
            }
        }

        #pragma unroll
        for (int k2 = 0; k2 < 16; k2++) {
            ulonglong2 b0 = *(const ulonglong2*)&Ws[2 * k2][tx * 4];
            ulonglong2 b1 = *(const ulonglong2*)&Ws[2 * k2 + 1][tx * 4];
            #pragma unroll
            for (int i = 0; i < 8; i++) {
                ulonglong2 a2 = *(const ulonglong2*)&Xs2[ty * 8 + i][2 * k2];
                ffma2(acc[i][0], a2.x, b0.x);
                ffma2(acc[i][1], a2.x, b0.y);
                ffma2(acc[i][0], a2.y, b1.x);
                ffma2(acc[i][1], a2.y, b1.y);
            }
        }
        __syncthreads();
    }

    const float4 bv4 = *(const float4*)&bias[tx * 4];
    #pragma unroll
    for (int i = 0; i < 8; i++) {
        int r = r0 + ty * 8 + i;
        float4 o;
        o.x = lo_f(acc[i][0]) + bv4.x;
        o.y = hi_f(acc[i][0]) + bv4.y;
        o.z = lo_f(acc[i][1]) + bv4.z;
        o.w = hi_f(acc[i][1]) + bv4.w;
        if (p == 0) {
            o.x = 1.f / (1.f + __expf(-o.x));
            o.y = 1.f / (1.f + __expf(-o.y));
            o.z = 1.f / (1.f + __expf(-o.z));
            o.w = 1.f / (1.f + __expf(-o.w));
        } else if (p == 1) {
            o.x = __expf(o.x); o.y = __expf(o.y);
            o.z = __expf(o.z); o.w = __expf(o.w);
        }
        *(float4*)&Out[r * DD + tx * 4] = o;
    }
}

// =============== kernel 2: C[b] = P @ M[b], fused out = q*num/den ===============
// NEW: 64 t-rows x 32 interleaved cols per block -> grid (8,8,4)=256 blocks,
// 2 CTAs/SM (16 warps/SM, 4/SMSP) to hide LDS latency. 256 threads:
// tx=tid&7 -> cols 4tx..4tx+3 (2 d-pairs), ty=tid>>3 (0..31) -> rows 2ty,2ty+1.
__global__ __launch_bounds__(256) void aft_kernel(float* __restrict__ out)
{
    __shared__ __align__(16) unsigned long long As2[64][34];   // 17.4 KB (expP pairs)
    __shared__ __align__(16) float Bs[32][36];                 //  4.6 KB

    const int b   = blockIdx.z;
    const int t0  = blockIdx.x * 64;
    const int c0  = blockIdx.y * 32;     // interleaved col tile (even)
    const int d0  = c0 >> 1;             // 16 d's per tile
    const int tid = threadIdx.x;
    const int tx  = tid & 7;
    const int ty  = tid >> 3;

    const float* Ek = g_Ek + b * NN * DD;
    const float* V  = g_V  + b * NN * DD;

    unsigned long long acc[2][2] = {};   // [row][colpair]; lo=num, hi=den
    ulonglong2 pa[4];
    float2 e2, v2;

    // prefetch K-tile 0
    {
        #pragma unroll
        for (int l = 0; l < 4; l++) {
            int idx = tid + l * 256, row = idx >> 4, k2i = idx & 15;
            pa[l] = *(const ulonglong2*)&g_P2[(t0 + row) * NN + 2 * k2i];
        }
        int jr = tid >> 3, dp = tid & 7;
        e2 = *(const float2*)&Ek[jr * DD + d0 + 2 * dp];
        v2 = *(const float2*)&V [jr * DD + d0 + 2 * dp];
    }

    for (int kt = 0; kt < 16; kt++) {
        // stores (regs -> smem)
        #pragma unroll
        for (int l = 0; l < 4; l++) {
            int idx = tid + l * 256, row = idx >> 4, k2i = idx & 15;
            *(ulonglong2*)&As2[row][2 * k2i] = pa[l];
        }
        {
            int jr = tid >> 3, dp = tid & 7;
            float4 w;
            w.x = e2.x * v2.x; w.y = e2.x;
            w.z = e2.y * v2.y; w.w = e2.y;
            *(float4*)&Bs[jr][4 * dp] = w;
        }
        __syncthreads();

        // prefetch next K-tile under the compute
        if (kt < 15) {
            int kk = (kt + 1) * 32;
            #pragma unroll
            for (int l = 0; l < 4; l++) {
                int idx = tid + l * 256, row = idx >> 4, k2i = idx & 15;
                pa[l] = *(const ulonglong2*)&g_P2[(t0 + row) * NN + kk + 2 * k2i];
            }
            int jr = tid >> 3, dp = tid & 7;
            e2 = *(const float2*)&Ek[(kk + jr) * DD + d0 + 2 * dp];
            v2 = *(const float2*)&V [(kk + jr) * DD + d0 + 2 * dp];
        }

        // compute: 2 k-steps/iter, 8 ffma2 per 4 LDS128
        #pragma unroll
        for (int k2 = 0; k2 < 16; k2++) {
            ulonglong2 b0 = *(const ulonglong2*)&Bs[2 * k2][tx * 4];
            ulonglong2 b1 = *(const ulonglong2*)&Bs[2 * k2 + 1][tx * 4];
            #pragma unroll
            for (int i = 0; i < 2; i++) {
                ulonglong2 a2 = *(const ulonglong2*)&As2[2 * ty + i][2 * k2];
                ffma2(acc[i][0], a2.x, b0.x);
                ffma2(acc[i][1], a2.x, b0.y);
                ffma2(acc[i][0], a2.y, b1.x);
                ffma2(acc[i][1], a2.y, b1.y);
            }
        }
        __syncthreads();
    }

    // fused epilogue: out = q * num / den
    const float* q  = g_q + b * NN * DD;
    const int    dd = d0 + 2 * tx;       // 2 consecutive d's per thread
    #pragma unroll
    for (int i = 0; i < 2; i++) {
        int t = t0 + 2 * ty + i;
        float num0 = lo_f(acc[i][0]), den0 = hi_f(acc[i][0]);
        float num1 = lo_f(acc[i][1]), den1 = hi_f(acc[i][1]);
        float2 qv = *(const float2*)&q[t * DD + dd];
        float2 o;
        o.x = qv.x * (num0 / den0);
        o.y = qv.y * (num1 / den1);
        *(float2*)&out[(b * NN + t) * DD + dd] = o;
    }
}

// ---------------- launch ----------------
extern "C" void kernel_launch(void* const* d_in, const int* in_sizes, int n_in,
                              void* d_out, int out_size) {
    const float* x  = (const float*)d_in[0];
    const float* Wq = (const float*)d_in[1];
    const float* bq = (const float*)d_in[2];
    const float* Wk = (const float*)d_in[3];
    const float* bk = (const float*)d_in[4];
    const float* Wv = (const float*)d_in[5];
    const float* bv = (const float*)d_in[6];
    const float* pb = (const float*)d_in[7];
    float* out = (float*)d_out;

    prep_kernel<<<160, 256>>>(x, Wq, bq, Wk, bk, Wv, bv, pb);
    aft_kernel<<<dim3(NN / 64, 8, BSZ), 256>>>(out);
}

// round 14
// speedup vs baseline: 1.6233x; 1.6233x over previous
#include <cuda_runtime.h>
#include <cuda_bf16.h>
#include <cstdint>

#define BSZ 4
#define NN  512
#define DD  128

// ---------------- scratch (no allocations allowed) ----------------
__device__ __align__(16) float g_q [BSZ * NN * DD];
__device__ __align__(16) float g_Ek[BSZ * NN * DD];
__device__ __align__(16) float g_V [BSZ * NN * DD];
__device__ __align__(16) unsigned short g_Phi[NN * NN];           // bf16 hi of exp(pos_bias)
__device__ __align__(16) unsigned short g_Plo[NN * NN];           // bf16 lo
__device__ __align__(16) unsigned short g_Bhi[BSZ * 2 * DD * NN]; // M^T hi: [b][c][j], c=interleave(num,den)
__device__ __align__(16) unsigned short g_Blo[BSZ * 2 * DD * NN]; // M^T lo

// ---------------- helpers ----------------
__device__ __forceinline__ void ffma2(unsigned long long& d,
                                      unsigned long long a,
                                      unsigned long long b) {
    asm("fma.rn.f32x2 %0, %1, %2, %0;" : "+l"(d) : "l"(a), "l"(b));
}
__device__ __forceinline__ unsigned long long dup_f32(float f) {
    unsigned int u = __float_as_uint(f);
    return ((unsigned long long)u << 32) | (unsigned long long)u;
}
__device__ __forceinline__ float lo_f(unsigned long long u) { return __uint_as_float((unsigned)u); }
__device__ __forceinline__ float hi_f(unsigned long long u) { return __uint_as_float((unsigned)(u >> 32)); }

// bf16 hi/lo split: x = hi + lo + O(2^-16 x)
__device__ __forceinline__ void split_bf16(float x, unsigned short& h, unsigned short& l) {
    __nv_bfloat16 hb = __float2bfloat16(x);
    float r = x - __bfloat162float(hb);
    __nv_bfloat16 lb = __float2bfloat16(r);
    h = __bfloat16_as_ushort(hb);
    l = __bfloat16_as_ushort(lb);
}

__device__ __forceinline__ uint32_t smem_u32(const void* p) {
    uint32_t a;
    asm("{ .reg .u64 t; cvta.to.shared.u64 t, %1; cvt.u32.u64 %0, t; }" : "=r"(a) : "l"(p));
    return a;
}
// portable tensor-core primitives (base PTX, ok on .target sm_103)
__device__ __forceinline__ void ldsm4(uint32_t& r0, uint32_t& r1, uint32_t& r2, uint32_t& r3,
                                      uint32_t addr) {
    asm volatile("ldmatrix.sync.aligned.m8n8.x4.shared.b16 {%0,%1,%2,%3}, [%4];"
                 : "=r"(r0), "=r"(r1), "=r"(r2), "=r"(r3) : "r"(addr));
}
__device__ __forceinline__ void mma16816(float* c, const uint32_t* a, const uint32_t* b) {
    asm volatile("mma.sync.aligned.m16n8k16.row.col.f32.bf16.bf16.f32 "
                 "{%0,%1,%2,%3}, {%4,%5,%6,%7}, {%8,%9}, {%0,%1,%2,%3};"
                 : "+f"(c[0]), "+f"(c[1]), "+f"(c[2]), "+f"(c[3])
                 : "r"(a[0]), "r"(a[1]), "r"(a[2]), "r"(a[3]), "r"(b[0]), "r"(b[1]));
}

// =============== kernel 1: fused projections (blocks 0..95) + exp(pos_bias) split (96..159) ===============
__global__ __launch_bounds__(256) void prep_kernel(
    const float* __restrict__ X,
    const float* __restrict__ Wq, const float* __restrict__ bq,
    const float* __restrict__ Wk, const float* __restrict__ bk,
    const float* __restrict__ Wv, const float* __restrict__ bv,
    const float* __restrict__ pb)
{
    const int tid = threadIdx.x;
    const int bx  = blockIdx.x;

    if (bx >= 96) {   // ---- exp(pos_bias) -> bf16 hi/lo planes ----
        const int base = (bx - 96) * 4096;
        #pragma unroll
        for (int l = 0; l < 4; l++) {
            int i = base + l * 1024 + tid * 4;
            float4 v = *(const float4*)&pb[i];
            ushort4 h, lo;
            split_bf16(__expf(v.x), h.x, lo.x);
            split_bf16(__expf(v.y), h.y, lo.y);
            split_bf16(__expf(v.z), h.z, lo.z);
            split_bf16(__expf(v.w), h.w, lo.w);
            *(ushort4*)&g_Phi[i] = h;
            *(ushort4*)&g_Plo[i] = lo;
        }
        return;
    }

    __shared__ __align__(16) unsigned long long Xs2[64][34];
    __shared__ __align__(16) float Ws[32][132];

    const int p  = bx >> 5;
    const int r0 = (bx & 31) * 64;
    const float* W    = (p == 0) ? Wq : (p == 1) ? Wk : Wv;
    const float* bias = (p == 0) ? bq : (p == 1) ? bk : bv;
    float*       Out  = (p == 0) ? g_q : (p == 1) ? g_Ek : g_V;

    const int tx = tid & 31;
    const int ty = tid >> 5;

    unsigned long long acc[8][2] = {};
    float4 ax[2], wx[4];

    #pragma unroll
    for (int l = 0; l < 2; l++) {
        int idx = tid + l * 256, row = idx >> 3, c4 = idx & 7;
        ax[l] = *(const float4*)&X[(r0 + row) * DD + 4 * c4];
    }
    #pragma unroll
    for (int l = 0; l < 4; l++) {
        int idx = tid + l * 256, k4 = idx & 7, e = idx >> 3;
        wx[l] = *(const float4*)&W[e * DD + 4 * k4];
    }

    for (int kt = 0; kt < 4; kt++) {
        #pragma unroll
        for (int l = 0; l < 2; l++) {
            int idx = tid + l * 256, row = idx >> 3, c4 = idx & 7;
            ulonglong2 u0, u1;
            u0.x = dup_f32(ax[l].x); u0.y = dup_f32(ax[l].y);
            u1.x = dup_f32(ax[l].z); u1.y = dup_f32(ax[l].w);
            *(ulonglong2*)&Xs2[row][4 * c4]     = u0;
            *(ulonglong2*)&Xs2[row][4 * c4 + 2] = u1;
        }
        #pragma unroll
        for (int l = 0; l < 4; l++) {
            int idx = tid + l * 256, k4 = idx & 7, e = idx >> 3;
            Ws[4 * k4 + 0][e] = wx[l].x;
            Ws[4 * k4 + 1][e] = wx[l].y;
            Ws[4 * k4 + 2][e] = wx[l].z;
            Ws[4 * k4 + 3][e] = wx[l].w;
        }
        __syncthreads();

        if (kt < 3) {
            int kk = (kt + 1) * 32;
            #pragma unroll
            for (int l = 0; l < 2; l++) {
                int idx = tid + l * 256, row = idx >> 3, c4 = idx & 7;
                ax[l] = *(const float4*)&X[(r0 + row) * DD + kk + 4 * c4];
            }
            #pragma unroll
            for (int l = 0; l < 4; l++) {
                int idx = tid + l * 256, k4 = idx & 7, e = idx >> 3;
                wx[l] = *(const float4*)&W[e * DD + kk + 4 * k4];
            }
        }

        #pragma unroll
        for (int k2 = 0; k2 < 16; k2++) {
            ulonglong2 b0 = *(const ulonglong2*)&Ws[2 * k2][tx * 4];
            ulonglong2 b1 = *(const ulonglong2*)&Ws[2 * k2 + 1][tx * 4];
            #pragma unroll
            for (int i = 0; i < 8; i++) {
                ulonglong2 a2 = *(const ulonglong2*)&Xs2[ty * 8 + i][2 * k2];
                ffma2(acc[i][0], a2.x, b0.x);
                ffma2(acc[i][1], a2.x, b0.y);
                ffma2(acc[i][0], a2.y, b1.x);
                ffma2(acc[i][1], a2.y, b1.y);
            }
        }
        __syncthreads();
    }

    const float4 bv4 = *(const float4*)&bias[tx * 4];
    #pragma unroll
    for (int i = 0; i < 8; i++) {
        int r = r0 + ty * 8 + i;
        float4 o;
        o.x = lo_f(acc[i][0]) + bv4.x;
        o.y = hi_f(acc[i][0]) + bv4.y;
        o.z = lo_f(acc[i][1]) + bv4.z;
        o.w = hi_f(acc[i][1]) + bv4.w;
        if (p == 0) {
            o.x = 1.f / (1.f + __expf(-o.x));
            o.y = 1.f / (1.f + __expf(-o.y));
            o.z = 1.f / (1.f + __expf(-o.z));
            o.w = 1.f / (1.f + __expf(-o.w));
        } else if (p == 1) {
            o.x = __expf(o.x); o.y = __expf(o.y);
            o.z = __expf(o.z); o.w = __expf(o.w);
        }
        *(float4*)&Out[r * DD + tx * 4] = o;
    }
}

// =============== kernel 2: build M^T bf16 hi/lo:  g_B[b][c][j],  c=2d -> Ek*V, c=2d+1 -> Ek ===============
__global__ __launch_bounds__(256) void conv_kernel() {
    __shared__ unsigned short Shi[64][66];
    __shared__ unsigned short Slo[64][66];
    const int tid = threadIdx.x;
    const int j0  = blockIdx.x * 64;
    const int d0  = blockIdx.y * 32;
    const int b   = blockIdx.z;
    const float* Ek = g_Ek + b * NN * DD;
    const float* V  = g_V  + b * NN * DD;

    #pragma unroll
    for (int l = 0; l < 8; l++) {
        int idx = tid + l * 256;
        int jr = idx >> 5, dc = idx & 31;
        float ek = Ek[(j0 + jr) * DD + d0 + dc];
        float vv = V [(j0 + jr) * DD + d0 + dc];
        unsigned short nh, nl, dh, dl;
        split_bf16(ek * vv, nh, nl);
        split_bf16(ek,      dh, dl);
        Shi[2 * dc][jr] = nh;     Slo[2 * dc][jr] = nl;
        Shi[2 * dc + 1][jr] = dh; Slo[2 * dc + 1][jr] = dl;
    }
    __syncthreads();

    const int c0 = 2 * d0;
    uint32_t* Bh = (uint32_t*)g_Bhi;
    uint32_t* Bl = (uint32_t*)g_Blo;
    #pragma unroll
    for (int l = 0; l < 8; l++) {
        int u = tid + l * 256;
        int c = u >> 5, jw = u & 31;
        uint32_t vh = *(const uint32_t*)&Shi[c][2 * jw];
        uint32_t vl = *(const uint32_t*)&Slo[c][2 * jw];
        int dst = (b * 256 + c0 + c) * 256 + (j0 >> 1) + jw;
        Bh[dst] = vh; Bl[dst] = vl;
    }
}

// =============== kernel 3: HMMA GEMM  C[128,32] = P_tile @ M^T_tile (hi/lo), fused epilogue ===============
// grid (4, 8, 4), 256 thr = 8 warps in 4(m) x 2(n); warp tile 32x16 = 2x2 m16n8k16 frags.
// A row-major (P), B col-major [c][j] (M^T) -> mma row.col, no transposes anywhere.
__global__ __launch_bounds__(256) void aft_mma_kernel(float* __restrict__ out) {
    __shared__ __align__(16) unsigned short Ahs[128][72];   // 18.0 KB (stride 144B: ldmatrix conflict-free)
    __shared__ __align__(16) unsigned short Als[128][72];
    __shared__ __align__(16) unsigned short Bhs[32][72];    //  4.5 KB
    __shared__ __align__(16) unsigned short Bls[32][72];

    const int tid = threadIdx.x;
    const int wid = tid >> 5, lane = tid & 31;
    const int wm = wid >> 1;          // 0..3 -> m offset 32*wm
    const int wn = wid & 1;           // 0..1 -> n offset 16*wn
    const int t0 = blockIdx.x * 128;
    const int n0 = blockIdx.y * 32;
    const int b  = blockIdx.z;

    const uint4* Phi = (const uint4*)g_Phi;   // 64 uint4 per 512-half row
    const uint4* Plo = (const uint4*)g_Plo;
    const uint4* Bhi = (const uint4*)g_Bhi;
    const uint4* Blo = (const uint4*)g_Blo;

    const uint32_t uAh = smem_u32(Ahs), uAl = smem_u32(Als);
    const uint32_t uBh = smem_u32(Bhs), uBl = smem_u32(Bls);

    float acc[2][2][4] = {};          // [m-frag][n-frag][c0..c3]; hh+hl+lh all accumulate here
    uint4 ah[4], al[4], bh, bl;

    // prefetch chunk 0 (64 k-halves = 8 uint4 per row)
    #pragma unroll
    for (int l = 0; l < 4; l++) {
        int s = tid + l * 256, row = s >> 3, su = s & 7;
        int src = (t0 + row) * 64 + su;
        ah[l] = Phi[src]; al[l] = Plo[src];
    }
    {
        int row = tid >> 3, su = tid & 7;
        int src = (b * 256 + n0 + row) * 64 + su;
        bh = Bhi[src]; bl = Blo[src];
    }

    // per-lane ldmatrix address components (bytes)
    const int aRow = wm * 32 + (lane & 15);          // + 16*i per m-frag
    const int aCol = (lane >> 4) << 3;               // halves; + 16*ks
    const int bRow = wn * 16 + ((lane >> 4) << 3) + (lane & 7);
    const int bCol = ((lane >> 3) & 1) << 3;         // halves; + 16*ks

    for (int c = 0; c < 8; c++) {
        // regs -> smem
        #pragma unroll
        for (int l = 0; l < 4; l++) {
            int s = tid + l * 256, row = s >> 3, su = s & 7;
            *(uint4*)&Ahs[row][su * 8] = ah[l];
            *(uint4*)&Als[row][su * 8] = al[l];
        }
        {
            int row = tid >> 3, su = tid & 7;
            *(uint4*)&Bhs[row][su * 8] = bh;
            *(uint4*)&Bls[row][su * 8] = bl;
        }
        __syncthreads();

        // prefetch next chunk under the MMA burst
        if (c < 7) {
            int kk = (c + 1) * 8;
            #pragma unroll
            for (int l = 0; l < 4; l++) {
                int s = tid + l * 256, row = s >> 3, su = s & 7;
                int src = (t0 + row) * 64 + kk + su;
                ah[l] = Phi[src]; al[l] = Plo[src];
            }
            int row = tid >> 3, su = tid & 7;
            int src = (b * 256 + n0 + row) * 64 + kk + su;
            bh = Bhi[src]; bl = Blo[src];
        }

        // 4 k16 steps: 6 ldmatrix.x4 + 12 mma each
        #pragma unroll
        for (int ks = 0; ks < 4; ks++) {
            const int kh = ks * 16;   // k offset in halves
            uint32_t fah[2][4], fal[2][4], fbh[4], fbl[4];
            #pragma unroll
            for (int i = 0; i < 2; i++) {
                uint32_t aoff = (uint32_t)((aRow + 16 * i) * 144 + (kh + aCol) * 2);
                ldsm4(fah[i][0], fah[i][1], fah[i][2], fah[i][3], uAh + aoff);
                ldsm4(fal[i][0], fal[i][1], fal[i][2], fal[i][3], uAl + aoff);
            }
            {
                uint32_t boff = (uint32_t)(bRow * 144 + (kh + bCol) * 2);
                ldsm4(fbh[0], fbh[1], fbh[2], fbh[3], uBh + boff);
                ldsm4(fbl[0], fbl[1], fbl[2], fbl[3], uBl + boff);
            }
            #pragma unroll
            for (int i = 0; i < 2; i++) {
                #pragma unroll
                for (int j = 0; j < 2; j++) {
                    mma16816(acc[i][j], fah[i], &fbh[2 * j]);   // hh
                    mma16816(acc[i][j], fah[i], &fbl[2 * j]);   // hl
                    mma16816(acc[i][j], fal[i], &fbh[2 * j]);   // lh
                }
            }
        }
        __syncthreads();
    }

    // fused epilogue: cols 2(l%4) even -> (c0,c1) = (num,den) of one d; rows r and r+8 via (c2,c3)
    const int gid  = lane >> 2, qid = lane & 3;
    const int dg   = (n0 >> 1) + wn * 8 + qid;        // + 4*j
    const int rA   = t0 + wm * 32 + gid;              // + 16*i, +8
    #pragma unroll
    for (int i = 0; i < 2; i++) {
        #pragma unroll
        for (int j = 0; j < 2; j++) {
            int t = rA + 16 * i;
            int d = dg + 4 * j;
            const float* qp = g_q + (b * NN + t) * DD + d;
            float*       op = out + (size_t)(b * NN + t) * DD + d;
            op[0]      = qp[0]      * (acc[i][j][0] / acc[i][j][1]);
            op[8 * DD] = qp[8 * DD] * (acc[i][j][2] / acc[i][j][3]);
        }
    }
}

// ---------------- launch ----------------
extern "C" void kernel_launch(void* const* d_in, const int* in_sizes, int n_in,
                              void* d_out, int out_size) {
    const float* x  = (const float*)d_in[0];
    const float* Wq = (const float*)d_in[1];
    const float* bq = (const float*)d_in[2];
    const float* Wk = (const float*)d_in[3];
    const float* bk = (const float*)d_in[4];
    const float* Wv = (const float*)d_in[5];
    const float* bv = (const float*)d_in[6];
    const float* pb = (const float*)d_in[7];
    float* out = (float*)d_out;

    prep_kernel<<<160, 256>>>(x, Wq, bq, Wk, bk, Wv, bv, pb);
    conv_kernel<<<dim3(8, 4, 4), 256>>>();
    aft_mma_kernel<<<dim3(4, 8, 4), 256>>>(out);
}